// round 4
// baseline (speedup 1.0000x reference)
#include <cuda_runtime.h>

typedef unsigned long long ull;

#define THREADS 512
#define SMEM_FLOATS 57344            // 3 quad arrays (3*4096*4) + 1 pair array (4096*2)
#define SMEM_BYTES  (SMEM_FLOATS * 4) // 229376 bytes

__device__ __forceinline__ ull pack2(float lo, float hi) {
    ull r; asm("mov.b64 %0, {%1, %2};" : "=l"(r) : "f"(lo), "f"(hi)); return r;
}
__device__ __forceinline__ void unpack2(ull v, float& lo, float& hi) {
    asm("mov.b64 {%0, %1}, %2;" : "=f"(lo), "=f"(hi) : "l"(v));
}
__device__ __forceinline__ ull mul2(ull a, ull b) {
    ull d; asm("mul.rn.f32x2 %0, %1, %2;" : "=l"(d) : "l"(a), "l"(b)); return d;
}
__device__ __forceinline__ ull fma2(ull a, ull b, ull c) {
    ull d; asm("fma.rn.f32x2 %0, %1, %2, %3;" : "=l"(d) : "l"(a), "l"(b), "l"(c)); return d;
}

// ANFIS restructured:
//   den[b]   = prod_i (sum_t mu[b,i,t])
//   G[b,j]   = sum_r w[b,r] * C[r,j]  (hierarchical partial products, base-4 digits)
//   out[b]   = (sum_j xa[b,j] * G[b,j]) / (den[b] + 1e-8)
// Each thread: TWO batch elements packed in f32x2, ONE QUARTER of the rule
// space (d0 = lane>>3). 16 warps/block = 4 warps/SMSP for latency hiding.
// Quarter-sums combined with shfl_xor(8) + shfl_xor(16).
__global__ void __launch_bounds__(THREADS, 1) anfis_kernel(
    const float* __restrict__ x,
    const float* __restrict__ centers,
    const float* __restrict__ sigmas,
    const float* __restrict__ cons,
    float* __restrict__ out,
    int half)
{
    extern __shared__ float sm[];
    // --- Build duplicated consequent table in SMEM ---
    //   [0      , 16384) : Q0[r] = (c0,c0,c1,c1)   (ulonglong2, 16B aligned)
    //   [16384  , 32768) : Q1[r] = (c2,c2,c3,c3)
    //   [32768  , 49152) : Q2[r] = (c4,c4,c5,c5)
    //   [49152  , 57344) : P6[r] = (c6,c6)          (ull, 8B aligned)
    for (int idx = threadIdx.x; idx < 4096 * 7; idx += THREADS) {
        int r = idx / 7;
        int j = idx - r * 7;
        float v = cons[idx];
        float* dst;
        if (j < 6) dst = sm + ((j >> 1) << 14) + r * 4 + ((j & 1) << 1);
        else       dst = sm + 49152 + r * 2;
        dst[0] = v;
        dst[1] = v;
    }

    int lane  = threadIdx.x & 31;
    int warp  = threadIdx.x >> 5;
    int qsel  = lane >> 3;                                  // 0..3: which d0 quarter
    int p     = blockIdx.x * 128 + warp * 8 + (lane & 7);   // batch pair id
    int b0 = p;
    int b1 = p + half;

    // --- Memberships for both elements (computed redundantly by all quarters) ---
    float xv0[6], xv1[6];
#pragma unroll
    for (int i = 0; i < 6; i++) { xv0[i] = x[b0 * 6 + i]; xv1[i] = x[b1 * 6 + i]; }

    ull lmu[12];                   // levels 0..2 (dynamic-indexed)
    ull rmu3[4], rmu4[4], rmu5[4]; // levels 3..5 (register-resident via unroll)
    float den0 = 1.0f, den1 = 1.0f;
#pragma unroll
    for (int i = 0; i < 6; i++) {
        float s0 = 0.0f, s1 = 0.0f;
#pragma unroll
        for (int tt = 0; tt < 4; tt++) {
            float c   = centers[i * 4 + tt];
            float sg  = fabsf(sigmas[i * 4 + tt]) + 1e-6f;
            float inv = 0.5f / (sg * sg);
            float d0v = xv0[i] - c;
            float d1v = xv1[i] - c;
            float m0  = __expf(-d0v * d0v * inv);
            float m1  = __expf(-d1v * d1v * inv);
            s0 += m0; s1 += m1;
            ull mp = pack2(m0, m1);
            if (i < 3)       lmu[i * 4 + tt] = mp;
            else if (i == 3) rmu3[tt] = mp;
            else if (i == 4) rmu4[tt] = mp;
            else             rmu5[tt] = mp;
        }
        den0 *= s0; den1 *= s1;
    }
    __syncthreads();

    const ulonglong2* Q0 = (const ulonglong2*)(sm);
    const ulonglong2* Q1 = (const ulonglong2*)(sm + 16384);
    const ulonglong2* Q2 = (const ulonglong2*)(sm + 32768);
    const ull*        P6 = (const ull*)(sm + 49152);

    ull acc0 = 0, acc1 = 0, acc2 = 0, acc3 = 0, acc4 = 0, acc5 = 0, acc6 = 0;

    // This thread covers d0 == qsel only: 1024 rules.
    ull A0 = lmu[qsel];
    int rb = qsel * 1024;
#pragma unroll 1
    for (int d1 = 0; d1 < 4; d1++) {
        ull A1 = mul2(A0, lmu[4 + d1]);
#pragma unroll 1
        for (int d2 = 0; d2 < 4; d2++) {
            ull A2 = mul2(A1, lmu[8 + d2]);
#pragma unroll
            for (int d3 = 0; d3 < 4; d3++) {
                ull A3 = mul2(A2, rmu3[d3]);
#pragma unroll
                for (int d4 = 0; d4 < 4; d4++) {
                    ull A4 = mul2(A3, rmu4[d4]);
#pragma unroll
                    for (int d5 = 0; d5 < 4; d5++) {
                        int rr = rb + d3 * 16 + d4 * 4 + d5;
                        ull w = mul2(A4, rmu5[d5]);
                        ulonglong2 q0 = Q0[rr];
                        ulonglong2 q1 = Q1[rr];
                        ulonglong2 q2 = Q2[rr];
                        ull        p6 = P6[rr];
                        acc0 = fma2(w, q0.x, acc0);
                        acc1 = fma2(w, q0.y, acc1);
                        acc2 = fma2(w, q1.x, acc2);
                        acc3 = fma2(w, q1.y, acc3);
                        acc4 = fma2(w, q2.x, acc4);
                        acc5 = fma2(w, q2.y, acc5);
                        acc6 = fma2(w, p6, acc6);
                    }
                }
            }
            rb += 64;
        }
    }

    // --- Combine the four rule-quarters within the warp (xor 8, xor 16) ---
    unsigned mask = 0xFFFFFFFFu;
    {
        float lo, hi;
        ull* accs[7] = { &acc0, &acc1, &acc2, &acc3, &acc4, &acc5, &acc6 };
#pragma unroll
        for (int j = 0; j < 7; j++) {
            unpack2(*accs[j], lo, hi);
            lo += __shfl_xor_sync(mask, lo, 8);
            hi += __shfl_xor_sync(mask, hi, 8);
            lo += __shfl_xor_sync(mask, lo, 16);
            hi += __shfl_xor_sync(mask, hi, 16);
            *accs[j] = pack2(lo, hi);
        }
    }

    // --- Epilogue: num = xa . G ; out = num / (den + 1e-8) ---
    if (qsel == 0) {
        float g0[7], g1[7];
        unpack2(acc0, g0[0], g1[0]);
        unpack2(acc1, g0[1], g1[1]);
        unpack2(acc2, g0[2], g1[2]);
        unpack2(acc3, g0[3], g1[3]);
        unpack2(acc4, g0[4], g1[4]);
        unpack2(acc5, g0[5], g1[5]);
        unpack2(acc6, g0[6], g1[6]);

        float n0 = g0[6], n1 = g1[6];
#pragma unroll
        for (int i = 0; i < 6; i++) { n0 += g0[i] * xv0[i]; n1 += g1[i] * xv1[i]; }

        out[b0] = n0 / (den0 + 1e-8f);
        out[b1] = n1 / (den1 + 1e-8f);
    }
}

extern "C" void kernel_launch(void* const* d_in, const int* in_sizes, int n_in,
                              void* d_out, int out_size) {
    const float* x       = (const float*)d_in[0];
    const float* centers = (const float*)d_in[1];
    const float* sigmas  = (const float*)d_in[2];
    const float* cons    = (const float*)d_in[3];
    float* out = (float*)d_out;

    int B    = in_sizes[0] / 6;   // 32768
    int half = B >> 1;            // 16384

    cudaFuncSetAttribute(anfis_kernel,
                         cudaFuncAttributeMaxDynamicSharedMemorySize, SMEM_BYTES);

    int blocks = 128;             // 128 pairs per block * 128 blocks = 16384 pairs
    anfis_kernel<<<blocks, THREADS, SMEM_BYTES>>>(x, centers, sigmas, cons, out, half);
}

// round 5
// speedup vs baseline: 1.7325x; 1.7325x over previous
#include <cuda_runtime.h>

typedef unsigned long long ull;

#define THREADS 256
#define SMEM_BYTES (7 * 4096 * 4)   // 114688: j-major table Cj[j][4096]

__device__ __forceinline__ ull pack2(float lo, float hi) {
    ull r; asm("mov.b64 %0, {%1, %2};" : "=l"(r) : "f"(lo), "f"(hi)); return r;
}
__device__ __forceinline__ void unpack2(ull v, float& lo, float& hi) {
    asm("mov.b64 {%0, %1}, %2;" : "=f"(lo), "=f"(hi) : "l"(v));
}
__device__ __forceinline__ ull mul2(ull a, ull b) {
    ull d; asm("mul.rn.f32x2 %0, %1, %2;" : "=l"(d) : "l"(a), "l"(b)); return d;
}
__device__ __forceinline__ ull fma2(ull a, ull b, ull c) {
    ull d; asm("fma.rn.f32x2 %0, %1, %2, %3;" : "=l"(d) : "l"(a), "l"(b), "l"(c)); return d;
}

// ANFIS restructured:
//   den[b] = prod_i (sum_t mu[b,i,t])
//   G[b,j] = sum_r w[b,r] * C[r,j]   (hierarchical partial products, base-4)
//   out[b] = (sum_j xa[b,j] * G[b,j]) / (den[b] + 1e-8)
// f32x2 SIMD now packs (rule r, rule r+1): multiplier pairs come straight
// from a j-major fp32 table (float4 = 4 rules of one j), zero duplication,
// all lanes in a warp read the SAME address -> pure broadcast LDS.
// One batch element per thread; 7 independent f32x2 accumulators (ILP 7).
__global__ void __launch_bounds__(THREADS, 1) anfis_kernel(
    const float* __restrict__ x,
    const float* __restrict__ centers,
    const float* __restrict__ sigmas,
    const float* __restrict__ cons,
    float* __restrict__ out)
{
    extern __shared__ float sm[];
    // --- Build j-major table: sm[j*4096 + r] = cons[r*7 + j] ---
    for (int idx = threadIdx.x; idx < 7 * 4096; idx += THREADS) {
        int j = idx >> 12;
        int r = idx & 4095;
        sm[idx] = cons[r * 7 + j];
    }

    int b = blockIdx.x * THREADS + threadIdx.x;

    // --- Memberships (this thread's element only) ---
    float xv[6];
#pragma unroll
    for (int i = 0; i < 6; i++) xv[i] = x[b * 6 + i];

    ull lmu[12];            // levels 0..2, duplicated pairs (dynamic idx -> local)
    ull rmu3d[4], rmu4d[4]; // levels 3..4, duplicated pairs (registers)
    ull mu5p01, mu5p23;     // level 5 as natural pairs (m0,m1), (m2,m3)
    float mu5v[4];
    float den = 1.0f;
#pragma unroll
    for (int i = 0; i < 6; i++) {
        float s = 0.0f;
#pragma unroll
        for (int tt = 0; tt < 4; tt++) {
            float c   = centers[i * 4 + tt];
            float sg  = fabsf(sigmas[i * 4 + tt]) + 1e-6f;
            float inv = 0.5f / (sg * sg);
            float dv  = xv[i] - c;
            float m   = __expf(-dv * dv * inv);
            s += m;
            if (i < 3)       lmu[i * 4 + tt] = pack2(m, m);
            else if (i == 3) rmu3d[tt] = pack2(m, m);
            else if (i == 4) rmu4d[tt] = pack2(m, m);
            else             mu5v[tt] = m;
        }
        den *= s;
    }
    mu5p01 = pack2(mu5v[0], mu5v[1]);
    mu5p23 = pack2(mu5v[2], mu5v[3]);
    __syncthreads();

    const float4* C4 = (const float4*)sm;   // C4[j*1024 + (r>>2)]

    ull acc0 = 0, acc1 = 0, acc2 = 0, acc3 = 0, acc4 = 0, acc5 = 0, acc6 = 0;

    int qbase = 0;   // quad index = r >> 2
#pragma unroll 1
    for (int d0 = 0; d0 < 4; d0++) {
        ull A0 = lmu[d0];
#pragma unroll 1
        for (int d1 = 0; d1 < 4; d1++) {
            ull A1 = mul2(A0, lmu[4 + d1]);
#pragma unroll 1
            for (int d2 = 0; d2 < 4; d2++) {
                ull A2 = mul2(A1, lmu[8 + d2]);
#pragma unroll
                for (int d3 = 0; d3 < 4; d3++) {
                    ull A3 = mul2(A2, rmu3d[d3]);
#pragma unroll
                    for (int d4 = 0; d4 < 4; d4++) {
                        ull A4  = mul2(A3, rmu4d[d4]);
                        ull w01 = mul2(A4, mu5p01);
                        ull w23 = mul2(A4, mu5p23);
                        int q = qbase + d3 * 4 + d4;    // quad of rules 4q..4q+3
                        float4 c0 = C4[q];
                        float4 c1 = C4[1024 + q];
                        float4 c2 = C4[2048 + q];
                        float4 c3 = C4[3072 + q];
                        float4 c4 = C4[4096 + q];
                        float4 c5 = C4[5120 + q];
                        float4 c6 = C4[6144 + q];
                        acc0 = fma2(w01, pack2(c0.x, c0.y), acc0);
                        acc1 = fma2(w01, pack2(c1.x, c1.y), acc1);
                        acc2 = fma2(w01, pack2(c2.x, c2.y), acc2);
                        acc3 = fma2(w01, pack2(c3.x, c3.y), acc3);
                        acc4 = fma2(w01, pack2(c4.x, c4.y), acc4);
                        acc5 = fma2(w01, pack2(c5.x, c5.y), acc5);
                        acc6 = fma2(w01, pack2(c6.x, c6.y), acc6);
                        acc0 = fma2(w23, pack2(c0.z, c0.w), acc0);
                        acc1 = fma2(w23, pack2(c1.z, c1.w), acc1);
                        acc2 = fma2(w23, pack2(c2.z, c2.w), acc2);
                        acc3 = fma2(w23, pack2(c3.z, c3.w), acc3);
                        acc4 = fma2(w23, pack2(c4.z, c4.w), acc4);
                        acc5 = fma2(w23, pack2(c5.z, c5.w), acc5);
                        acc6 = fma2(w23, pack2(c6.z, c6.w), acc6);
                    }
                }
                qbase += 16;
            }
        }
    }

    // --- Epilogue: g[j] = lo+hi of acc_j; out = (xa.g) / (den + 1e-8) ---
    float lo, hi, g[7];
    unpack2(acc0, lo, hi); g[0] = lo + hi;
    unpack2(acc1, lo, hi); g[1] = lo + hi;
    unpack2(acc2, lo, hi); g[2] = lo + hi;
    unpack2(acc3, lo, hi); g[3] = lo + hi;
    unpack2(acc4, lo, hi); g[4] = lo + hi;
    unpack2(acc5, lo, hi); g[5] = lo + hi;
    unpack2(acc6, lo, hi); g[6] = lo + hi;

    float num = g[6];
#pragma unroll
    for (int i = 0; i < 6; i++) num += g[i] * xv[i];

    out[b] = num / (den + 1e-8f);
}

extern "C" void kernel_launch(void* const* d_in, const int* in_sizes, int n_in,
                              void* d_out, int out_size) {
    const float* x       = (const float*)d_in[0];
    const float* centers = (const float*)d_in[1];
    const float* sigmas  = (const float*)d_in[2];
    const float* cons    = (const float*)d_in[3];
    float* out = (float*)d_out;

    int B = in_sizes[0] / 6;        // 32768
    int blocks = B / THREADS;       // 128

    cudaFuncSetAttribute(anfis_kernel,
                         cudaFuncAttributeMaxDynamicSharedMemorySize, SMEM_BYTES);

    anfis_kernel<<<blocks, THREADS, SMEM_BYTES>>>(x, centers, sigmas, cons, out);
}

// round 6
// speedup vs baseline: 1.8416x; 1.0630x over previous
#include <cuda_runtime.h>

typedef unsigned long long ull;

#define THREADS 512
#define TABLE_FLOATS (7 * 4096)                 // 28672 floats = 114688 B
#define RED_FLOATS   (256 * 7)                  // 7168 B staging for half-combine
#define SMEM_BYTES   ((TABLE_FLOATS + RED_FLOATS) * 4)  // 121856 B

__device__ __forceinline__ ull pack2(float lo, float hi) {
    ull r; asm("mov.b64 %0, {%1, %2};" : "=l"(r) : "f"(lo), "f"(hi)); return r;
}
__device__ __forceinline__ void unpack2(ull v, float& lo, float& hi) {
    asm("mov.b64 {%0, %1}, %2;" : "=f"(lo), "=f"(hi) : "l"(v));
}
__device__ __forceinline__ ull mul2(ull a, ull b) {
    ull d; asm("mul.rn.f32x2 %0, %1, %2;" : "=l"(d) : "l"(a), "l"(b)); return d;
}
__device__ __forceinline__ ull fma2(ull a, ull b, ull c) {
    ull d; asm("fma.rn.f32x2 %0, %1, %2, %3;" : "=l"(d) : "l"(a), "l"(b), "l"(c)); return d;
}

// ANFIS restructured:
//   den[b] = prod_i (sum_t mu[b,i,t])
//   G[b,j] = sum_r w[b,r] * C[r,j]   (hierarchical partial products, base-4)
//   out[b] = (sum_j xa[b,j] * G[b,j]) / (den[b] + 1e-8)
// f32x2 packs (rule r, rule r+1); coefficients come from a j-major fp32 table
// (float4 = 4 rules of one j), every warp reads uniform broadcast addresses.
// WARP-level rule split: warps 0-7 handle d0 in {0,1}, warps 8-15 d0 in {2,3},
// for the same 256 elements; halves combined via a smem staging buffer.
// 16 warps/block = 4 warps/SMSP for latency hiding with zero extra LDS cost.
__global__ void __launch_bounds__(THREADS, 1) anfis_kernel(
    const float* __restrict__ x,
    const float* __restrict__ centers,
    const float* __restrict__ sigmas,
    const float* __restrict__ cons,
    float* __restrict__ out)
{
    extern __shared__ float sm[];
    float* red = sm + TABLE_FLOATS;

    // --- Build j-major table: sm[j*4096 + r] = cons[r*7 + j] ---
    for (int idx = threadIdx.x; idx < TABLE_FLOATS; idx += THREADS) {
        int j = idx >> 12;
        int r = idx & 4095;
        sm[idx] = cons[r * 7 + j];
    }

    int lane = threadIdx.x & 31;
    int warp = threadIdx.x >> 5;
    int h    = warp >> 3;                 // 0 or 1: which d0 half
    int e    = (warp & 7) * 32 + lane;    // element slot within block (0..255)
    int b    = blockIdx.x * 256 + e;

    // --- Memberships (this thread's element; computed by both halves) ---
    float xv[6];
#pragma unroll
    for (int i = 0; i < 6; i++) xv[i] = x[b * 6 + i];

    ull lmu[12];            // levels 0..2, duplicated pairs (dynamic idx -> local)
    ull rmu3d[4], rmu4d[4]; // levels 3..4, duplicated pairs (registers)
    ull mu5p01, mu5p23;     // level 5 as natural pairs (m0,m1), (m2,m3)
    float mu5v[4];
    float den = 1.0f;
#pragma unroll
    for (int i = 0; i < 6; i++) {
        float s = 0.0f;
#pragma unroll
        for (int tt = 0; tt < 4; tt++) {
            float c   = centers[i * 4 + tt];
            float sg  = fabsf(sigmas[i * 4 + tt]) + 1e-6f;
            float inv = 0.5f / (sg * sg);
            float dv  = xv[i] - c;
            float m   = __expf(-dv * dv * inv);
            s += m;
            if (i < 3)       lmu[i * 4 + tt] = pack2(m, m);
            else if (i == 3) rmu3d[tt] = pack2(m, m);
            else if (i == 4) rmu4d[tt] = pack2(m, m);
            else             mu5v[tt] = m;
        }
        den *= s;
    }
    mu5p01 = pack2(mu5v[0], mu5v[1]);
    mu5p23 = pack2(mu5v[2], mu5v[3]);
    __syncthreads();

    const float4* C4 = (const float4*)sm;   // C4[j*1024 + (r>>2)]

    ull acc0 = 0, acc1 = 0, acc2 = 0, acc3 = 0, acc4 = 0, acc5 = 0, acc6 = 0;

    int d0_start = h * 2;
#pragma unroll 1
    for (int d0 = d0_start; d0 < d0_start + 2; d0++) {
        ull A0 = lmu[d0];
        int qb0 = d0 * 256;
#pragma unroll 1
        for (int d1 = 0; d1 < 4; d1++) {
            ull A1 = mul2(A0, lmu[4 + d1]);
#pragma unroll 1
            for (int d2 = 0; d2 < 4; d2++) {
                ull A2 = mul2(A1, lmu[8 + d2]);
                int qbase = qb0 + d1 * 64 + d2 * 16;
#pragma unroll
                for (int d3 = 0; d3 < 4; d3++) {
                    ull A3 = mul2(A2, rmu3d[d3]);
#pragma unroll
                    for (int d4 = 0; d4 < 4; d4++) {
                        ull A4  = mul2(A3, rmu4d[d4]);
                        ull w01 = mul2(A4, mu5p01);
                        ull w23 = mul2(A4, mu5p23);
                        int q = qbase + d3 * 4 + d4;    // quad of rules 4q..4q+3
                        float4 c0 = C4[q];
                        float4 c1 = C4[1024 + q];
                        float4 c2 = C4[2048 + q];
                        float4 c3 = C4[3072 + q];
                        float4 c4 = C4[4096 + q];
                        float4 c5 = C4[5120 + q];
                        float4 c6 = C4[6144 + q];
                        acc0 = fma2(w01, pack2(c0.x, c0.y), acc0);
                        acc1 = fma2(w01, pack2(c1.x, c1.y), acc1);
                        acc2 = fma2(w01, pack2(c2.x, c2.y), acc2);
                        acc3 = fma2(w01, pack2(c3.x, c3.y), acc3);
                        acc4 = fma2(w01, pack2(c4.x, c4.y), acc4);
                        acc5 = fma2(w01, pack2(c5.x, c5.y), acc5);
                        acc6 = fma2(w01, pack2(c6.x, c6.y), acc6);
                        acc0 = fma2(w23, pack2(c0.z, c0.w), acc0);
                        acc1 = fma2(w23, pack2(c1.z, c1.w), acc1);
                        acc2 = fma2(w23, pack2(c2.z, c2.w), acc2);
                        acc3 = fma2(w23, pack2(c3.z, c3.w), acc3);
                        acc4 = fma2(w23, pack2(c4.z, c4.w), acc4);
                        acc5 = fma2(w23, pack2(c5.z, c5.w), acc5);
                        acc6 = fma2(w23, pack2(c6.z, c6.w), acc6);
                    }
                }
            }
        }
    }

    // --- Reduce f32x2 pair -> scalar per j ---
    float lo, hi, g[7];
    unpack2(acc0, lo, hi); g[0] = lo + hi;
    unpack2(acc1, lo, hi); g[1] = lo + hi;
    unpack2(acc2, lo, hi); g[2] = lo + hi;
    unpack2(acc3, lo, hi); g[3] = lo + hi;
    unpack2(acc4, lo, hi); g[4] = lo + hi;
    unpack2(acc5, lo, hi); g[5] = lo + hi;
    unpack2(acc6, lo, hi); g[6] = lo + hi;

    // --- Combine the two halves via smem (stride 7 -> conflict-free) ---
    if (h == 1) {
#pragma unroll
        for (int j = 0; j < 7; j++) red[e * 7 + j] = g[j];
    }
    __syncthreads();
    if (h == 0) {
#pragma unroll
        for (int j = 0; j < 7; j++) g[j] += red[e * 7 + j];

        float num = g[6];
#pragma unroll
        for (int i = 0; i < 6; i++) num += g[i] * xv[i];

        out[b] = num / (den + 1e-8f);
    }
}

extern "C" void kernel_launch(void* const* d_in, const int* in_sizes, int n_in,
                              void* d_out, int out_size) {
    const float* x       = (const float*)d_in[0];
    const float* centers = (const float*)d_in[1];
    const float* sigmas  = (const float*)d_in[2];
    const float* cons    = (const float*)d_in[3];
    float* out = (float*)d_out;

    int B = in_sizes[0] / 6;        // 32768
    int blocks = B / 256;           // 128 (256 elements per block)

    cudaFuncSetAttribute(anfis_kernel,
                         cudaFuncAttributeMaxDynamicSharedMemorySize, SMEM_BYTES);

    anfis_kernel<<<blocks, THREADS, SMEM_BYTES>>>(x, centers, sigmas, cons, out);
}

// round 7
// speedup vs baseline: 2.1580x; 1.1718x over previous
#include <cuda_runtime.h>

typedef unsigned long long ull;

#define THREADS 512
#define TABLE_FLOATS (7 * 4096)              // j-major coefficient table
#define RED_FLOATS   (7 * 64 * 29)           // 7 octants x 64 quads x 29-float rows
#define SMEM_BYTES   ((TABLE_FLOATS + RED_FLOATS) * 4)   // 166656 B

__device__ __forceinline__ ull pack2(float lo, float hi) {
    ull r; asm("mov.b64 %0, {%1, %2};" : "=l"(r) : "f"(lo), "f"(hi)); return r;
}
__device__ __forceinline__ void unpack2(ull v, float& lo, float& hi) {
    asm("mov.b64 {%0, %1}, %2;" : "=f"(lo), "=f"(hi) : "l"(v));
}
__device__ __forceinline__ ull mul2(ull a, ull b) {
    ull d; asm("mul.rn.f32x2 %0, %1, %2;" : "=l"(d) : "l"(a), "l"(b)); return d;
}
__device__ __forceinline__ ull fma2(ull a, ull b, ull c) {
    ull d; asm("fma.rn.f32x2 %0, %1, %2, %3;" : "=l"(d) : "l"(a), "l"(b), "l"(c)); return d;
}

// ANFIS restructured:
//   den[b] = prod_i (sum_t mu[b,i,t])
//   G[b,j] = sum_r w[b,r] * C[r,j]
//   out[b] = (sum_j xa[b,j] * G[b,j]) / (den[b] + 1e-8)
// f32x2 packs ELEMENTS: thread carries 4 batch elements as two (b,b') pairs.
// Coefficients (element-invariant) are loaded once per float4 (4 rules, 1 j)
// and register-duplicated -> each LDS.128 feeds 8 FFMA2. l1tex traffic drops
// 4x vs rule-packing; kernel lands on the f32x2 FMA-pipe roofline.
// 16 warps/block: warp = (rule-octant rs 0..7) x (quad-group g 0..1).
// Octant = fixed d0, half of d1. Octant partials combined via smem staging.
__global__ void __launch_bounds__(THREADS, 1) anfis_kernel(
    const float* __restrict__ x,
    const float* __restrict__ centers,
    const float* __restrict__ sigmas,
    const float* __restrict__ cons,
    float* __restrict__ out)
{
    extern __shared__ float sm[];
    float* red = sm + TABLE_FLOATS;

    // --- Build j-major table: sm[j*4096 + r] = cons[r*7 + j] ---
    for (int idx = threadIdx.x; idx < TABLE_FLOATS; idx += THREADS) {
        int j = idx >> 12;
        int r = idx & 4095;
        sm[idx] = cons[r * 7 + j];
    }

    int lane = threadIdx.x & 31;
    int warp = threadIdx.x >> 5;
    int g    = warp & 1;            // which 32-quad group
    int rs   = warp >> 1;           // rule octant 0..7
    int d0   = rs >> 1;             // fixed level-0 digit
    int d1h  = rs & 1;              // which half of level-1 digits
    int quad = g * 32 + lane;       // 0..63 within block
    int q    = blockIdx.x * 64 + quad;

    int b0 = q, b1 = q + 8192, b2 = q + 16384, b3 = q + 24576;

    // --- Memberships for 4 elements; pairs: P=(b0,b1), Q=(b2,b3) ---
    float xv0[6], xv1[6], xv2[6], xv3[6];
#pragma unroll
    for (int i = 0; i < 6; i++) {
        xv0[i] = x[b0 * 6 + i];
        xv1[i] = x[b1 * 6 + i];
        xv2[i] = x[b2 * 6 + i];
        xv3[i] = x[b3 * 6 + i];
    }

    ull A0P = 0, A0Q = 0;                 // mu0[d0]
    ull m1P[2], m1Q[2];                   // mu1 at d1h*2 + {0,1}
    ull mu2P[4], mu2Q[4], mu3P[4], mu3Q[4];
    ull mu4P[4], mu4Q[4], mu5P[4], mu5Q[4];
    float den0 = 1.0f, den1 = 1.0f, den2 = 1.0f, den3 = 1.0f;

#pragma unroll
    for (int i = 0; i < 6; i++) {
        float s0 = 0.0f, s1 = 0.0f, s2 = 0.0f, s3 = 0.0f;
#pragma unroll
        for (int t = 0; t < 4; t++) {
            float c   = centers[i * 4 + t];
            float sg  = fabsf(sigmas[i * 4 + t]) + 1e-6f;
            float inv = 0.5f / (sg * sg);
            float e0 = xv0[i] - c, e1 = xv1[i] - c, e2 = xv2[i] - c, e3 = xv3[i] - c;
            float m0 = __expf(-e0 * e0 * inv);
            float m1 = __expf(-e1 * e1 * inv);
            float m2 = __expf(-e2 * e2 * inv);
            float m3 = __expf(-e3 * e3 * inv);
            s0 += m0; s1 += m1; s2 += m2; s3 += m3;
            ull P = pack2(m0, m1);
            ull Q = pack2(m2, m3);
            if (i == 0) { if (t == d0) { A0P = P; A0Q = Q; } }
            else if (i == 1) {
                if (t == d1h * 2)     { m1P[0] = P; m1Q[0] = Q; }
                if (t == d1h * 2 + 1) { m1P[1] = P; m1Q[1] = Q; }
            }
            else if (i == 2) { mu2P[t] = P; mu2Q[t] = Q; }
            else if (i == 3) { mu3P[t] = P; mu3Q[t] = Q; }
            else if (i == 4) { mu4P[t] = P; mu4Q[t] = Q; }
            else             { mu5P[t] = P; mu5Q[t] = Q; }
        }
        den0 *= s0; den1 *= s1; den2 *= s2; den3 *= s3;
    }
    __syncthreads();

    const float4* C4 = (const float4*)sm;   // C4[j*1024 + quadIdx]

    ull accP[7], accQ[7];
#pragma unroll
    for (int j = 0; j < 7; j++) { accP[j] = 0; accQ[j] = 0; }

#pragma unroll 1
    for (int d1i = 0; d1i < 2; d1i++) {
        ull A1P = mul2(A0P, m1P[d1i]);
        ull A1Q = mul2(A0Q, m1Q[d1i]);
        int d1 = d1h * 2 + d1i;
#pragma unroll 1
        for (int d2 = 0; d2 < 4; d2++) {
            ull A2P = mul2(A1P, mu2P[d2]);
            ull A2Q = mul2(A1Q, mu2Q[d2]);
#pragma unroll 1
            for (int d3 = 0; d3 < 4; d3++) {
                ull A3P = mul2(A2P, mu3P[d3]);
                ull A3Q = mul2(A2Q, mu3Q[d3]);
                int qb = d0 * 256 + d1 * 64 + d2 * 16 + d3 * 4;
#pragma unroll
                for (int d4 = 0; d4 < 4; d4++) {
                    ull A4P = mul2(A3P, mu4P[d4]);
                    ull A4Q = mul2(A3Q, mu4Q[d4]);
                    ull wP0 = mul2(A4P, mu5P[0]);
                    ull wP1 = mul2(A4P, mu5P[1]);
                    ull wP2 = mul2(A4P, mu5P[2]);
                    ull wP3 = mul2(A4P, mu5P[3]);
                    ull wQ0 = mul2(A4Q, mu5Q[0]);
                    ull wQ1 = mul2(A4Q, mu5Q[1]);
                    ull wQ2 = mul2(A4Q, mu5Q[2]);
                    ull wQ3 = mul2(A4Q, mu5Q[3]);
                    int qq = qb + d4;
#pragma unroll
                    for (int j = 0; j < 7; j++) {
                        float4 c = C4[j * 1024 + qq];
                        ull c0 = pack2(c.x, c.x);
                        ull c1 = pack2(c.y, c.y);
                        ull c2 = pack2(c.z, c.z);
                        ull c3 = pack2(c.w, c.w);
                        accP[j] = fma2(wP0, c0, accP[j]);
                        accQ[j] = fma2(wQ0, c0, accQ[j]);
                        accP[j] = fma2(wP1, c1, accP[j]);
                        accQ[j] = fma2(wQ1, c1, accQ[j]);
                        accP[j] = fma2(wP2, c2, accP[j]);
                        accQ[j] = fma2(wQ2, c2, accQ[j]);
                        accP[j] = fma2(wP3, c3, accP[j]);
                        accQ[j] = fma2(wQ3, c3, accQ[j]);
                    }
                }
            }
        }
    }

    // --- Combine 8 rule-octants per quad: octants 1..7 stage to smem ---
    if (rs != 0) {
        float* base = red + ((rs - 1) * 64 + quad) * 29;
#pragma unroll
        for (int j = 0; j < 7; j++) {
            float a, bf, c2, d2v;
            unpack2(accP[j], a, bf);
            unpack2(accQ[j], c2, d2v);
            base[j * 4 + 0] = a;
            base[j * 4 + 1] = bf;
            base[j * 4 + 2] = c2;
            base[j * 4 + 3] = d2v;
        }
    }
    __syncthreads();

    if (rs == 0) {
        float g0[7], g1[7], g2[7], g3[7];
#pragma unroll
        for (int j = 0; j < 7; j++) {
            unpack2(accP[j], g0[j], g1[j]);
            unpack2(accQ[j], g2[j], g3[j]);
        }
#pragma unroll 1
        for (int o = 0; o < 7; o++) {
            const float* base = red + (o * 64 + quad) * 29;
#pragma unroll
            for (int j = 0; j < 7; j++) {
                g0[j] += base[j * 4 + 0];
                g1[j] += base[j * 4 + 1];
                g2[j] += base[j * 4 + 2];
                g3[j] += base[j * 4 + 3];
            }
        }
        float n0 = g0[6], n1 = g1[6], n2 = g2[6], n3 = g3[6];
#pragma unroll
        for (int i = 0; i < 6; i++) {
            n0 += g0[i] * xv0[i];
            n1 += g1[i] * xv1[i];
            n2 += g2[i] * xv2[i];
            n3 += g3[i] * xv3[i];
        }
        out[b0] = n0 / (den0 + 1e-8f);
        out[b1] = n1 / (den1 + 1e-8f);
        out[b2] = n2 / (den2 + 1e-8f);
        out[b3] = n3 / (den3 + 1e-8f);
    }
}

extern "C" void kernel_launch(void* const* d_in, const int* in_sizes, int n_in,
                              void* d_out, int out_size) {
    const float* x       = (const float*)d_in[0];
    const float* centers = (const float*)d_in[1];
    const float* sigmas  = (const float*)d_in[2];
    const float* cons    = (const float*)d_in[3];
    float* out = (float*)d_out;

    int B = in_sizes[0] / 6;        // 32768
    int blocks = B / 256;           // 128 (64 quads = 256 elements per block)

    cudaFuncSetAttribute(anfis_kernel,
                         cudaFuncAttributeMaxDynamicSharedMemorySize, SMEM_BYTES);

    anfis_kernel<<<blocks, THREADS, SMEM_BYTES>>>(x, centers, sigmas, cons, out);
}